// round 1
// baseline (speedup 1.0000x reference)
#include <cuda_runtime.h>
#include <cuda_bf16.h>

// Problem constants (from reference): N=50000 nodes, D=256, HS=32 (96 output cols), E=1.6M edges
#define MAXN 50048
#define MAXE 1600000

// Scratch (static device globals; no allocation at runtime)
__device__ float g_Q[MAXN * 32];
__device__ float g_K[MAXN * 32];
__device__ float g_V[MAXN * 32];
__device__ int   g_cnt[MAXN];
__device__ int   g_off[MAXN + 1];
__device__ int   g_cur[MAXN];
__device__ int   g_sorted[MAXE];

// ---------------------------------------------------------------------------
// Kernel 0: zero counters
// ---------------------------------------------------------------------------
__global__ void zero_cnt_kernel(int n) {
    int i = blockIdx.x * blockDim.x + threadIdx.x;
    if (i < n) g_cnt[i] = 0;
}

// ---------------------------------------------------------------------------
// Kernel 1: fused QKV projection  [N,256] x [256,96] -> Q,K,V [N,32] each
// Register-tiled fp32 GEMM. Block = 256 threads (32 tx x 8 ty).
// Tile: 128 nodes x 96 cols. Microtile per thread: 4(m) x 12(j).
// ---------------------------------------------------------------------------
#define QKV_TM 128
#define QKV_KC 32

__global__ __launch_bounds__(256) void qkv_kernel(
    const float* __restrict__ X,
    const float* __restrict__ Wq,
    const float* __restrict__ Wk,
    const float* __restrict__ Wv,
    int nNodes)
{
    __shared__ float Xs[QKV_KC][QKV_TM + 4];  // transposed: Xs[k][m]
    __shared__ float Ws[QKV_KC][96];          // combined [Wq|Wk|Wv]

    const int tid = threadIdx.x;
    const int tx  = tid & 31;   // m dimension (4 rows each)
    const int ty  = tid >> 5;   // j dimension (12 cols each)
    const int m0  = blockIdx.x * QKV_TM;

    float acc[4][12];
    #pragma unroll
    for (int i = 0; i < 4; ++i)
        #pragma unroll
        for (int j = 0; j < 12; ++j) acc[i][j] = 0.f;

    for (int kc = 0; kc < 256; kc += QKV_KC) {
        // --- stage X tile (128 rows x 32 k), transposed into Xs[k][m] ---
        // warp ty loads rows ty*16 .. ty*16+15; per iter: 4 rows x 8 float4 (coalesced)
        #pragma unroll
        for (int it = 0; it < 4; ++it) {
            int row = ty * 16 + it * 4 + (tx >> 3);
            int kq  = tx & 7;
            int gm  = m0 + row;
            float4 v = make_float4(0.f, 0.f, 0.f, 0.f);
            if (gm < nNodes)
                v = *reinterpret_cast<const float4*>(&X[gm * 256 + kc + kq * 4]);
            int kk = kq * 4;
            Xs[kk + 0][row] = v.x;
            Xs[kk + 1][row] = v.y;
            Xs[kk + 2][row] = v.z;
            Xs[kk + 3][row] = v.w;
        }
        // --- stage W tile (32 k x 96 j) ---
        for (int idx = tid; idx < QKV_KC * 96; idx += 256) {
            int k = idx / 96, j = idx % 96;
            const float* Wp = (j < 32) ? Wq : ((j < 64) ? Wk : Wv);
            Ws[k][j] = Wp[(kc + k) * 32 + (j & 31)];
        }
        __syncthreads();

        #pragma unroll 4
        for (int k = 0; k < QKV_KC; ++k) {
            float4 a  = *reinterpret_cast<const float4*>(&Xs[k][tx * 4]);
            float4 b0 = *reinterpret_cast<const float4*>(&Ws[k][ty * 12]);
            float4 b1 = *reinterpret_cast<const float4*>(&Ws[k][ty * 12 + 4]);
            float4 b2 = *reinterpret_cast<const float4*>(&Ws[k][ty * 12 + 8]);
            float av[4] = {a.x, a.y, a.z, a.w};
            float bv[12] = {b0.x, b0.y, b0.z, b0.w,
                            b1.x, b1.y, b1.z, b1.w,
                            b2.x, b2.y, b2.z, b2.w};
            #pragma unroll
            for (int i = 0; i < 4; ++i)
                #pragma unroll
                for (int j = 0; j < 12; ++j)
                    acc[i][j] += av[i] * bv[j];
        }
        __syncthreads();
    }

    // --- epilogue: scatter into g_Q / g_K / g_V ---
    #pragma unroll
    for (int i = 0; i < 4; ++i) {
        int node = m0 + tx * 4 + i;
        if (node >= nNodes) continue;
        #pragma unroll
        for (int j = 0; j < 12; ++j) {
            int jj  = ty * 12 + j;
            int col = jj & 31;
            float* dst = (jj < 32) ? g_Q : ((jj < 64) ? g_K : g_V);
            dst[node * 32 + col] = acc[i][j];
        }
    }
}

// ---------------------------------------------------------------------------
// Kernel 2: histogram of destination (row) nodes
// ---------------------------------------------------------------------------
__global__ void hist_kernel(const int* __restrict__ ei, int nEdges) {
    int e = blockIdx.x * blockDim.x + threadIdx.x;
    if (e < nEdges) atomicAdd(&g_cnt[ei[e]], 1);
}

// ---------------------------------------------------------------------------
// Kernel 3: exclusive prefix scan (single block, 1024 threads) -> offsets+cursor
// ---------------------------------------------------------------------------
__global__ void scan_kernel(int n) {
    __shared__ int sh[1024];
    int t = threadIdx.x;
    int carry = 0;
    for (int base = 0; base < n; base += 1024) {
        int i = base + t;
        int v = (i < n) ? g_cnt[i] : 0;
        sh[t] = v;
        __syncthreads();
        // Kogge-Stone inclusive scan
        for (int off = 1; off < 1024; off <<= 1) {
            int x = (t >= off) ? sh[t - off] : 0;
            __syncthreads();
            sh[t] += x;
            __syncthreads();
        }
        if (i < n) {
            int excl = carry + sh[t] - v;
            g_off[i] = excl;
            g_cur[i] = excl;
        }
        int tot = sh[1023];
        __syncthreads();
        carry += tot;
    }
    if (t == 0) g_off[n] = carry;
}

// ---------------------------------------------------------------------------
// Kernel 4: scatter source nodes into per-destination contiguous runs
// ---------------------------------------------------------------------------
__global__ void scatter_kernel(const int* __restrict__ ei, int nEdges) {
    int e = blockIdx.x * blockDim.x + threadIdx.x;
    if (e < nEdges) {
        int r = ei[e];
        int c = ei[nEdges + e];
        int pos = atomicAdd(&g_cur[r], 1);
        g_sorted[pos] = c;
    }
}

// ---------------------------------------------------------------------------
// Kernel 5: per-node attention. One warp per node; lane = head-dim element.
// Softmax without max-subtraction (algebraically identical; scores are O(10)).
// ---------------------------------------------------------------------------
__global__ __launch_bounds__(256) void attn_kernel(float* __restrict__ out, int nNodes) {
    int warp = (blockIdx.x * blockDim.x + threadIdx.x) >> 5;
    int lane = threadIdx.x & 31;
    if (warp >= nNodes) return;

    int s = g_off[warp];
    int e = g_off[warp + 1];

    // fold 1/sqrt(32) into q
    float q = g_Q[warp * 32 + lane] * 0.17677669529663687f;

    float denom = 0.f;
    float acc   = 0.f;

    for (int base = s; base < e; base += 32) {
        int n  = min(32, e - base);
        int cb = (base + lane < e) ? g_sorted[base + lane] : 0;
        for (int i = 0; i < n; ++i) {
            int c = __shfl_sync(0xffffffffu, cb, i);
            float kv = g_K[c * 32 + lane];
            float vv = g_V[c * 32 + lane];
            float p  = q * kv;
            // full butterfly reduce: every lane ends with the dot product
            p += __shfl_xor_sync(0xffffffffu, p, 16);
            p += __shfl_xor_sync(0xffffffffu, p, 8);
            p += __shfl_xor_sync(0xffffffffu, p, 4);
            p += __shfl_xor_sync(0xffffffffu, p, 2);
            p += __shfl_xor_sync(0xffffffffu, p, 1);
            float ex = __expf(p);
            denom += ex;
            acc   += ex * vv;
        }
    }

    out[warp * 32 + lane] = (e > s) ? (acc / denom) : 0.f;
}

// ---------------------------------------------------------------------------
// Launch
// ---------------------------------------------------------------------------
extern "C" void kernel_launch(void* const* d_in, const int* in_sizes, int n_in,
                              void* d_out, int out_size)
{
    const float* X  = (const float*)d_in[0];
    const float* Wq = (const float*)d_in[1];
    const float* Wk = (const float*)d_in[2];
    const float* Wv = (const float*)d_in[3];
    const int*   ei = (const int*)d_in[4];
    float* out = (float*)d_out;

    const int N = in_sizes[0] / 256;   // 50000
    const int E = in_sizes[4] / 2;     // 1600000

    // 0: zero counters
    zero_cnt_kernel<<<(N + 255) / 256, 256>>>(N);
    // 1: QKV projection
    qkv_kernel<<<(N + QKV_TM - 1) / QKV_TM, 256>>>(X, Wq, Wk, Wv, N);
    // 2: histogram
    hist_kernel<<<(E + 255) / 256, 256>>>(ei, E);
    // 3: scan
    scan_kernel<<<1, 1024>>>(N);
    // 4: scatter (counting sort by destination node)
    scatter_kernel<<<(E + 255) / 256, 256>>>(ei, E);
    // 5: attention + aggregation
    attn_kernel<<<(N * 32 + 255) / 256, 256>>>(out, N);
}

// round 2
// speedup vs baseline: 1.2457x; 1.2457x over previous
#include <cuda_runtime.h>
#include <cuda_bf16.h>

// Problem constants: N=50000 nodes, D=256, HS=32, E=1.6M edges
#define MAXN 50048
#define MAXE 1600000

// Scratch (static device globals; no runtime allocation)
__device__ float g_Q[MAXN * 32];
__device__ float g_K[MAXN * 32];
__device__ float g_V[MAXN * 32];
__device__ int   g_cnt[MAXN];
__device__ int   g_off[MAXN + 1];
__device__ int   g_cur[MAXN];
__device__ int   g_sorted[MAXE];
__device__ int   g_bsum[64];
__device__ int   g_bbase[64];

// ---------------------------------------------------------------------------
// Kernel 0: zero counters
// ---------------------------------------------------------------------------
__global__ void zero_cnt_kernel(int n) {
    int i = blockIdx.x * blockDim.x + threadIdx.x;
    if (i < n) g_cnt[i] = 0;
}

// ---------------------------------------------------------------------------
// Kernel 1: fused QKV projection  [N,256] x [256,96] -> Q,K,V [N,32] each
// 128 threads, tile 128 rows x 96 cols, microtile 8x12, packed fma.rn.f32x2.
// ---------------------------------------------------------------------------
#define QKV_TM 128

__global__ __launch_bounds__(128) void qkv_kernel(
    const float* __restrict__ X,
    const float* __restrict__ Wq,
    const float* __restrict__ Wk,
    const float* __restrict__ Wv,
    int nNodes)
{
    __shared__ float Xs[32][QKV_TM + 4];  // transposed: Xs[k][m]
    __shared__ float Ws[32][96];          // combined [Wq|Wk|Wv]

    const int tid = threadIdx.x;
    const int tx  = tid & 15;   // 16 -> 8 rows each (tx*4 and 64+tx*4 groups)
    const int ty  = tid >> 4;   // 8  -> 12 cols each
    const int m0  = blockIdx.x * QKV_TM;

    unsigned long long accp[8][6];  // packed f32x2 accumulators (=96 floats)
    #pragma unroll
    for (int i = 0; i < 8; ++i)
        #pragma unroll
        for (int j = 0; j < 6; ++j) accp[i][j] = 0ull;

    for (int kc = 0; kc < 256; kc += 32) {
        // stage X tile: 128 rows x 32 k, transposed
        #pragma unroll
        for (int it = 0; it < 8; ++it) {
            int idx = it * 128 + tid;     // 0..1023
            int row = idx >> 3;
            int kq  = idx & 7;
            int gm  = m0 + row;
            float4 v = make_float4(0.f, 0.f, 0.f, 0.f);
            if (gm < nNodes)
                v = *reinterpret_cast<const float4*>(&X[gm * 256 + kc + kq * 4]);
            int kk = kq * 4;
            Xs[kk + 0][row] = v.x;
            Xs[kk + 1][row] = v.y;
            Xs[kk + 2][row] = v.z;
            Xs[kk + 3][row] = v.w;
        }
        // stage W tile (32 k x 96 j)
        #pragma unroll
        for (int idx = tid; idx < 32 * 96; idx += 128) {
            int k = idx / 96, j = idx - k * 96;
            const float* Wp = (j < 32) ? Wq : ((j < 64) ? Wk : Wv);
            Ws[k][j] = Wp[(kc + k) * 32 + (j & 31)];
        }
        __syncthreads();

        #pragma unroll
        for (int k = 0; k < 32; ++k) {
            float4 a0 = *reinterpret_cast<const float4*>(&Xs[k][tx * 4]);
            float4 a1 = *reinterpret_cast<const float4*>(&Xs[k][64 + tx * 4]);
            ulonglong2 b01 = *reinterpret_cast<const ulonglong2*>(&Ws[k][ty * 12]);
            ulonglong2 b23 = *reinterpret_cast<const ulonglong2*>(&Ws[k][ty * 12 + 4]);
            ulonglong2 b45 = *reinterpret_cast<const ulonglong2*>(&Ws[k][ty * 12 + 8]);
            unsigned long long bb[6] = {b01.x, b01.y, b23.x, b23.y, b45.x, b45.y};
            float av[8] = {a0.x, a0.y, a0.z, a0.w, a1.x, a1.y, a1.z, a1.w};
            #pragma unroll
            for (int i = 0; i < 8; ++i) {
                unsigned long long ad;
                asm("mov.b64 %0, {%1, %1};" : "=l"(ad) : "f"(av[i]));
                #pragma unroll
                for (int j = 0; j < 6; ++j)
                    asm("fma.rn.f32x2 %0, %1, %2, %0;"
                        : "+l"(accp[i][j]) : "l"(ad), "l"(bb[j]));
            }
        }
        __syncthreads();
    }

    // epilogue: rows i<4 -> m0+tx*4+i ; i>=4 -> m0+64+tx*4+(i-4)
    #pragma unroll
    for (int i = 0; i < 8; ++i) {
        int node = m0 + ((i < 4) ? (tx * 4 + i) : (64 + tx * 4 + i - 4));
        if (node >= nNodes) continue;
        #pragma unroll
        for (int j2 = 0; j2 < 6; ++j2) {
            float2 p = *reinterpret_cast<float2*>(&accp[i][j2]);
            int jj = ty * 12 + j2 * 2;
            float* dst0 = (jj < 32) ? g_Q : ((jj < 64) ? g_K : g_V);
            int jj1 = jj + 1;
            float* dst1 = (jj1 < 32) ? g_Q : ((jj1 < 64) ? g_K : g_V);
            dst0[node * 32 + (jj & 31)]  = p.x;
            dst1[node * 32 + (jj1 & 31)] = p.y;
        }
    }
}

// ---------------------------------------------------------------------------
// Kernel 2: histogram of destination (row) nodes
// ---------------------------------------------------------------------------
__global__ void hist_kernel(const int* __restrict__ ei, int nEdges) {
    int e = blockIdx.x * blockDim.x + threadIdx.x;
    if (e < nEdges) atomicAdd(&g_cnt[ei[e]], 1);
}

// ---------------------------------------------------------------------------
// Kernel 3a/3b/3c: hierarchical exclusive scan (chunks of 1024, <=64 blocks)
// ---------------------------------------------------------------------------
__global__ __launch_bounds__(1024) void scan_sum_kernel(int n) {
    int i = blockIdx.x * 1024 + threadIdx.x;
    int v = (i < n) ? g_cnt[i] : 0;
    #pragma unroll
    for (int o = 16; o; o >>= 1) v += __shfl_xor_sync(~0u, v, o);
    __shared__ int ws[32];
    if ((threadIdx.x & 31) == 0) ws[threadIdx.x >> 5] = v;
    __syncthreads();
    if (threadIdx.x < 32) {
        int s = ws[threadIdx.x];
        #pragma unroll
        for (int o = 16; o; o >>= 1) s += __shfl_xor_sync(~0u, s, o);
        if (threadIdx.x == 0) g_bsum[blockIdx.x] = s;
    }
}

__global__ void scan_base_kernel(int nb, int n) {
    __shared__ int sh[64];
    int t = threadIdx.x;
    int v = (t < nb) ? g_bsum[t] : 0;
    sh[t] = v;
    __syncthreads();
    #pragma unroll
    for (int o = 1; o < 64; o <<= 1) {
        int x = (t >= o) ? sh[t - o] : 0;
        __syncthreads();
        sh[t] += x;
        __syncthreads();
    }
    if (t < nb) g_bbase[t] = sh[t] - v;  // exclusive base per block
    if (t == 63) g_off[n] = sh[63];      // total edge count
}

__global__ __launch_bounds__(1024) void scan_write_kernel(int n) {
    int i = blockIdx.x * 1024 + threadIdx.x;
    int lane = threadIdx.x & 31, w = threadIdx.x >> 5;
    int v = (i < n) ? g_cnt[i] : 0;
    int x = v;
    #pragma unroll
    for (int o = 1; o < 32; o <<= 1) {
        int y = __shfl_up_sync(~0u, x, o);
        if (lane >= o) x += y;
    }
    __shared__ int ws[32];
    if (lane == 31) ws[w] = x;
    __syncthreads();
    if (w == 0) {
        int s = ws[lane];
        #pragma unroll
        for (int o = 1; o < 32; o <<= 1) {
            int y = __shfl_up_sync(~0u, s, o);
            if (lane >= o) s += y;
        }
        ws[lane] = s;
    }
    __syncthreads();
    int base = g_bbase[blockIdx.x] + (w ? ws[w - 1] : 0);
    if (i < n) {
        int excl = base + x - v;
        g_off[i] = excl;
        g_cur[i] = excl;
    }
}

// ---------------------------------------------------------------------------
// Kernel 4: scatter source nodes into per-destination contiguous runs
// ---------------------------------------------------------------------------
__global__ void scatter_kernel(const int* __restrict__ ei, int nEdges) {
    int e = blockIdx.x * blockDim.x + threadIdx.x;
    if (e < nEdges) {
        int r = ei[e];
        int c = ei[nEdges + e];
        int pos = atomicAdd(&g_cur[r], 1);
        g_sorted[pos] = c;
    }
}

// ---------------------------------------------------------------------------
// Kernel 5: per-node attention. One warp per node.
// Stage 32 K rows to smem (coalesced), each lane scores its own neighbor:
// 1 MUFU + 5 SHFL per 32 edges instead of per edge.
// ---------------------------------------------------------------------------
__global__ __launch_bounds__(256) void attn_kernel(float* __restrict__ out, int nNodes) {
    __shared__ float Ksh[8][32][33];
    __shared__ float qsh[8][32];
    __shared__ float exsh[8][32];
    __shared__ int   idxsh[8][32];

    const int wIn  = threadIdx.x >> 5;
    const int lane = threadIdx.x & 31;
    const int node = blockIdx.x * 8 + wIn;
    if (node >= nNodes) return;

    const int s = g_off[node];
    const int e = g_off[node + 1];

    float q = g_Q[node * 32 + lane] * 0.17677669529663687f;  // 1/sqrt(32)
    qsh[wIn][lane] = q;

    float denom = 0.f, acc = 0.f;
    float (*Kw)[33] = Ksh[wIn];

    for (int base = s; base < e; base += 32) {
        int n = min(32, e - base);
        idxsh[wIn][lane] = (base + lane < e) ? g_sorted[base + lane] : 0;
        __syncwarp();

        // stage K rows (coalesced 128B loads, deep MLP)
        #pragma unroll 4
        for (int i = 0; i < n; ++i)
            Kw[i][lane] = g_K[idxsh[wIn][i] * 32 + lane];
        __syncwarp();

        // each lane scores its own neighbor (conflict-free [32][33] reads)
        float ex = 0.f;
        if (lane < n) {
            float sc = 0.f;
            #pragma unroll
            for (int d = 0; d < 32; ++d)
                sc += qsh[wIn][d] * Kw[lane][d];
            ex = __expf(sc);
        }
        exsh[wIn][lane] = ex;

        float t = ex;
        t += __shfl_xor_sync(~0u, t, 16);
        t += __shfl_xor_sync(~0u, t, 8);
        t += __shfl_xor_sync(~0u, t, 4);
        t += __shfl_xor_sync(~0u, t, 2);
        t += __shfl_xor_sync(~0u, t, 1);
        denom += t;
        __syncwarp();

        // weighted V accumulation (coalesced 128B loads)
        #pragma unroll 4
        for (int i = 0; i < n; ++i)
            acc += exsh[wIn][i] * g_V[idxsh[wIn][i] * 32 + lane];
        __syncwarp();
    }

    out[node * 32 + lane] = (e > s) ? (acc / denom) : 0.f;
}

// ---------------------------------------------------------------------------
// Launch
// ---------------------------------------------------------------------------
extern "C" void kernel_launch(void* const* d_in, const int* in_sizes, int n_in,
                              void* d_out, int out_size)
{
    const float* X  = (const float*)d_in[0];
    const float* Wq = (const float*)d_in[1];
    const float* Wk = (const float*)d_in[2];
    const float* Wv = (const float*)d_in[3];
    const int*   ei = (const int*)d_in[4];
    float* out = (float*)d_out;

    const int N = in_sizes[0] / 256;   // 50000
    const int E = in_sizes[4] / 2;     // 1600000
    const int NB = (N + 1023) / 1024;  // 49 scan blocks (<=64)

    zero_cnt_kernel<<<(N + 255) / 256, 256>>>(N);
    qkv_kernel<<<(N + QKV_TM - 1) / QKV_TM, 128>>>(X, Wq, Wk, Wv, N);
    hist_kernel<<<(E + 255) / 256, 256>>>(ei, E);
    scan_sum_kernel<<<NB, 1024>>>(N);
    scan_base_kernel<<<1, 64>>>(NB, N);
    scan_write_kernel<<<NB, 1024>>>(N);
    scatter_kernel<<<(E + 255) / 256, 256>>>(ei, E);
    attn_kernel<<<(N + 7) / 8, 256>>>(out, N);
}

// round 3
// speedup vs baseline: 1.3745x; 1.1034x over previous
#include <cuda_runtime.h>
#include <cuda_bf16.h>

// Problem constants: N=50000 nodes, D=256, HS=32, E=1.6M edges
#define MAXN 50048
#define MAXE 1600000

// Scratch (static device globals; no runtime allocation)
__device__ float g_Q[MAXN * 32];
__device__ float g_K[MAXN * 32];
__device__ float g_V[MAXN * 32];
__device__ int   g_cnt[MAXN];
__device__ int   g_off[MAXN + 1];
__device__ int   g_cur[MAXN];
__device__ int   g_sorted[MAXE];
__device__ int   g_bsum[64];
__device__ int   g_bbase[64];

// ---------------------------------------------------------------------------
// Kernel 0: zero counters
// ---------------------------------------------------------------------------
__global__ void zero_cnt_kernel(int n) {
    int i = blockIdx.x * blockDim.x + threadIdx.x;
    if (i < n) g_cnt[i] = 0;
}

// ---------------------------------------------------------------------------
// Kernel 1: fused QKV projection  [N,256] x [256,96] -> Q,K,V [N,32] each
// 128 threads, tile 128 rows x 96 cols, microtile 8x12, packed fma.rn.f32x2.
// Q is pre-scaled by 1/sqrt(32) in the epilogue.
// ---------------------------------------------------------------------------
#define QKV_TM 128

__global__ __launch_bounds__(128) void qkv_kernel(
    const float* __restrict__ X,
    const float* __restrict__ Wq,
    const float* __restrict__ Wk,
    const float* __restrict__ Wv,
    int nNodes)
{
    __shared__ float Xs[32][QKV_TM + 4];  // transposed: Xs[k][m]
    __shared__ float Ws[32][96];          // combined [Wq|Wk|Wv]

    const int tid = threadIdx.x;
    const int tx  = tid & 15;   // 16 -> 8 rows each
    const int ty  = tid >> 4;   // 8  -> 12 cols each
    const int m0  = blockIdx.x * QKV_TM;

    unsigned long long accp[8][6];
    #pragma unroll
    for (int i = 0; i < 8; ++i)
        #pragma unroll
        for (int j = 0; j < 6; ++j) accp[i][j] = 0ull;

    for (int kc = 0; kc < 256; kc += 32) {
        #pragma unroll
        for (int it = 0; it < 8; ++it) {
            int idx = it * 128 + tid;
            int row = idx >> 3;
            int kq  = idx & 7;
            int gm  = m0 + row;
            float4 v = make_float4(0.f, 0.f, 0.f, 0.f);
            if (gm < nNodes)
                v = *reinterpret_cast<const float4*>(&X[gm * 256 + kc + kq * 4]);
            int kk = kq * 4;
            Xs[kk + 0][row] = v.x;
            Xs[kk + 1][row] = v.y;
            Xs[kk + 2][row] = v.z;
            Xs[kk + 3][row] = v.w;
        }
        #pragma unroll
        for (int idx = tid; idx < 32 * 96; idx += 128) {
            int k = idx / 96, j = idx - k * 96;
            const float* Wp = (j < 32) ? Wq : ((j < 64) ? Wk : Wv);
            Ws[k][j] = Wp[(kc + k) * 32 + (j & 31)];
        }
        __syncthreads();

        #pragma unroll
        for (int k = 0; k < 32; ++k) {
            float4 a0 = *reinterpret_cast<const float4*>(&Xs[k][tx * 4]);
            float4 a1 = *reinterpret_cast<const float4*>(&Xs[k][64 + tx * 4]);
            ulonglong2 b01 = *reinterpret_cast<const ulonglong2*>(&Ws[k][ty * 12]);
            ulonglong2 b23 = *reinterpret_cast<const ulonglong2*>(&Ws[k][ty * 12 + 4]);
            ulonglong2 b45 = *reinterpret_cast<const ulonglong2*>(&Ws[k][ty * 12 + 8]);
            unsigned long long bb[6] = {b01.x, b01.y, b23.x, b23.y, b45.x, b45.y};
            float av[8] = {a0.x, a0.y, a0.z, a0.w, a1.x, a1.y, a1.z, a1.w};
            #pragma unroll
            for (int i = 0; i < 8; ++i) {
                unsigned long long ad;
                asm("mov.b64 %0, {%1, %1};" : "=l"(ad) : "f"(av[i]));
                #pragma unroll
                for (int j = 0; j < 6; ++j)
                    asm("fma.rn.f32x2 %0, %1, %2, %0;"
                        : "+l"(accp[i][j]) : "l"(ad), "l"(bb[j]));
            }
        }
        __syncthreads();
    }

    const float qscale = 0.17677669529663687f;  // 1/sqrt(32)
    #pragma unroll
    for (int i = 0; i < 8; ++i) {
        int node = m0 + ((i < 4) ? (tx * 4 + i) : (64 + tx * 4 + i - 4));
        if (node >= nNodes) continue;
        #pragma unroll
        for (int j2 = 0; j2 < 6; ++j2) {
            float2 p = *reinterpret_cast<float2*>(&accp[i][j2]);
            int jj = ty * 12 + j2 * 2;   // even; pair never crosses a 32-col boundary
            float* dst = (jj < 32) ? g_Q : ((jj < 64) ? g_K : g_V);
            if (jj < 32) { p.x *= qscale; p.y *= qscale; }
            dst[node * 32 + (jj & 31)]     = p.x;
            dst[node * 32 + (jj & 31) + 1] = p.y;
        }
    }
}

// ---------------------------------------------------------------------------
// Kernel 2: histogram of destination nodes (int4, 4 edges/thread)
// ---------------------------------------------------------------------------
__global__ void hist_kernel(const int* __restrict__ ei, int nEdges) {
    int i = blockIdx.x * blockDim.x + threadIdx.x;
    int e4 = i * 4;
    if (e4 + 3 < nEdges) {
        int4 r = *reinterpret_cast<const int4*>(&ei[e4]);
        atomicAdd(&g_cnt[r.x], 1);
        atomicAdd(&g_cnt[r.y], 1);
        atomicAdd(&g_cnt[r.z], 1);
        atomicAdd(&g_cnt[r.w], 1);
    } else {
        for (int e = e4; e < nEdges; ++e) atomicAdd(&g_cnt[ei[e]], 1);
    }
}

// ---------------------------------------------------------------------------
// Kernel 3a/3b/3c: hierarchical exclusive scan
// ---------------------------------------------------------------------------
__global__ __launch_bounds__(1024) void scan_sum_kernel(int n) {
    int i = blockIdx.x * 1024 + threadIdx.x;
    int v = (i < n) ? g_cnt[i] : 0;
    #pragma unroll
    for (int o = 16; o; o >>= 1) v += __shfl_xor_sync(~0u, v, o);
    __shared__ int ws[32];
    if ((threadIdx.x & 31) == 0) ws[threadIdx.x >> 5] = v;
    __syncthreads();
    if (threadIdx.x < 32) {
        int s = ws[threadIdx.x];
        #pragma unroll
        for (int o = 16; o; o >>= 1) s += __shfl_xor_sync(~0u, s, o);
        if (threadIdx.x == 0) g_bsum[blockIdx.x] = s;
    }
}

__global__ void scan_base_kernel(int nb, int n) {
    __shared__ int sh[64];
    int t = threadIdx.x;
    int v = (t < nb) ? g_bsum[t] : 0;
    sh[t] = v;
    __syncthreads();
    #pragma unroll
    for (int o = 1; o < 64; o <<= 1) {
        int x = (t >= o) ? sh[t - o] : 0;
        __syncthreads();
        sh[t] += x;
        __syncthreads();
    }
    if (t < nb) g_bbase[t] = sh[t] - v;
    if (t == 63) g_off[n] = sh[63];
}

__global__ __launch_bounds__(1024) void scan_write_kernel(int n) {
    int i = blockIdx.x * 1024 + threadIdx.x;
    int lane = threadIdx.x & 31, w = threadIdx.x >> 5;
    int v = (i < n) ? g_cnt[i] : 0;
    int x = v;
    #pragma unroll
    for (int o = 1; o < 32; o <<= 1) {
        int y = __shfl_up_sync(~0u, x, o);
        if (lane >= o) x += y;
    }
    __shared__ int ws[32];
    if (lane == 31) ws[w] = x;
    __syncthreads();
    if (w == 0) {
        int s = ws[lane];
        #pragma unroll
        for (int o = 1; o < 32; o <<= 1) {
            int y = __shfl_up_sync(~0u, s, o);
            if (lane >= o) s += y;
        }
        ws[lane] = s;
    }
    __syncthreads();
    int base = g_bbase[blockIdx.x] + (w ? ws[w - 1] : 0);
    if (i < n) {
        int excl = base + x - v;
        g_off[i] = excl;
        g_cur[i] = excl;
    }
}

// ---------------------------------------------------------------------------
// Kernel 4: scatter source nodes (int4, 4 edges/thread)
// ---------------------------------------------------------------------------
__global__ void scatter_kernel(const int* __restrict__ ei, int nEdges) {
    int i = blockIdx.x * blockDim.x + threadIdx.x;
    int e4 = i * 4;
    if (e4 + 3 < nEdges) {
        int4 r = *reinterpret_cast<const int4*>(&ei[e4]);
        int4 c = *reinterpret_cast<const int4*>(&ei[nEdges + e4]);
        g_sorted[atomicAdd(&g_cur[r.x], 1)] = c.x;
        g_sorted[atomicAdd(&g_cur[r.y], 1)] = c.y;
        g_sorted[atomicAdd(&g_cur[r.z], 1)] = c.z;
        g_sorted[atomicAdd(&g_cur[r.w], 1)] = c.w;
    } else {
        for (int e = e4; e < nEdges; ++e)
            g_sorted[atomicAdd(&g_cur[ei[e]], 1)] = ei[nEdges + e];
    }
}

// ---------------------------------------------------------------------------
// Kernel 5: per-node attention. One warp per node.
// Edge indices live in registers (shfl-broadcast). K staged via 8 independent
// LDG.128 (MLP=8) into pad-33 smem (conflict-free scalar stores+reads).
// V gathered directly with shfl-broadcast weights.
// ---------------------------------------------------------------------------
__global__ __launch_bounds__(256) void attn_kernel(float* __restrict__ out, int nNodes) {
    __shared__ float Ksh[8][32][33];
    __shared__ float qsh[8][32];

    const int wIn  = threadIdx.x >> 5;
    const int lane = threadIdx.x & 31;
    const int node = blockIdx.x * 8 + wIn;
    if (node >= nNodes) return;

    const int s = g_off[node];
    const int e = g_off[node + 1];

    qsh[wIn][lane] = g_Q[node * 32 + lane];   // already scaled by 1/sqrt(32)
    float (*Kw)[33] = Ksh[wIn];

    float denom = 0.f, acc = 0.f;

    for (int base = s; base < e; base += 32) {
        const int n = min(32, e - base);
        int cb = (base + lane < e) ? g_sorted[base + lane] : -1;

        // stage K: 8 independent float4 loads (4 rows per warp-instr)
        #pragma unroll
        for (int it = 0; it < 8; ++it) {
            int row = it * 4 + (lane >> 3);
            int c   = __shfl_sync(~0u, cb, row);
            float4 kv = make_float4(0.f, 0.f, 0.f, 0.f);
            if (c >= 0)
                kv = *reinterpret_cast<const float4*>(&g_K[c * 32 + (lane & 7) * 4]);
            int col = (lane & 7) * 4;
            Kw[row][col + 0] = kv.x;
            Kw[row][col + 1] = kv.y;
            Kw[row][col + 2] = kv.z;
            Kw[row][col + 3] = kv.w;
        }
        __syncwarp();

        // each lane scores its own neighbor
        float ex = 0.f;
        if (lane < n) {
            float sc = 0.f;
            #pragma unroll
            for (int d = 0; d < 32; ++d)
                sc += qsh[wIn][d] * Kw[lane][d];
            ex = __expf(sc);
        }

        float t = ex;
        t += __shfl_xor_sync(~0u, t, 16);
        t += __shfl_xor_sync(~0u, t, 8);
        t += __shfl_xor_sync(~0u, t, 4);
        t += __shfl_xor_sync(~0u, t, 2);
        t += __shfl_xor_sync(~0u, t, 1);
        denom += t;

        // weighted V accumulation: shfl-broadcast idx + weight, coalesced LDG
        #pragma unroll 8
        for (int i = 0; i < n; ++i) {
            int   c = __shfl_sync(~0u, cb, i);
            float w = __shfl_sync(~0u, ex, i);
            acc += w * g_V[c * 32 + lane];
        }
        __syncwarp();
    }

    out[node * 32 + lane] = (e > s) ? (acc / denom) : 0.f;
}

// ---------------------------------------------------------------------------
// Launch
// ---------------------------------------------------------------------------
extern "C" void kernel_launch(void* const* d_in, const int* in_sizes, int n_in,
                              void* d_out, int out_size)
{
    const float* X  = (const float*)d_in[0];
    const float* Wq = (const float*)d_in[1];
    const float* Wk = (const float*)d_in[2];
    const float* Wv = (const float*)d_in[3];
    const int*   ei = (const int*)d_in[4];
    float* out = (float*)d_out;

    const int N = in_sizes[0] / 256;   // 50000
    const int E = in_sizes[4] / 2;     // 1600000
    const int NB = (N + 1023) / 1024;  // <=64 scan blocks
    const int E4 = (E + 3) / 4;

    zero_cnt_kernel<<<(N + 255) / 256, 256>>>(N);
    qkv_kernel<<<(N + QKV_TM - 1) / QKV_TM, 128>>>(X, Wq, Wk, Wv, N);
    hist_kernel<<<(E4 + 255) / 256, 256>>>(ei, E);
    scan_sum_kernel<<<NB, 1024>>>(N);
    scan_base_kernel<<<1, 64>>>(NB, N);
    scan_write_kernel<<<NB, 1024>>>(N);
    scatter_kernel<<<(E4 + 255) / 256, 256>>>(ei, E);
    attn_kernel<<<(N + 7) / 8, 256>>>(out, N);
}

// round 4
// speedup vs baseline: 1.7619x; 1.2818x over previous
#include <cuda_runtime.h>
#include <cuda_bf16.h>

// Problem constants: N=50000 nodes, D=256, HS=32, E=1.6M edges
#define MAXN 50048
#define MAXE 1600000

__device__ float g_Q[MAXN * 32];
__device__ float g_K[MAXN * 32];
__device__ float g_V[MAXN * 32];
__device__ int   g_cnt[MAXN];
__device__ int   g_off[MAXN + 1];
__device__ int   g_cur[MAXN];
__device__ int   g_sorted[MAXE];
__device__ int   g_bsum[64];
__device__ int   g_bbase[64];

// ---------------------------------------------------------------------------
__global__ void zero_cnt_kernel(int n) {
    int i = blockIdx.x * blockDim.x + threadIdx.x;
    if (i < n) g_cnt[i] = 0;
}

// ---------------------------------------------------------------------------
// QKV projection (unchanged from R3): 128 thr, tile 128x96, f32x2 FMAs.
// ---------------------------------------------------------------------------
#define QKV_TM 128

__global__ __launch_bounds__(128) void qkv_kernel(
    const float* __restrict__ X,
    const float* __restrict__ Wq,
    const float* __restrict__ Wk,
    const float* __restrict__ Wv,
    int nNodes)
{
    __shared__ float Xs[32][QKV_TM + 4];
    __shared__ float Ws[32][96];

    const int tid = threadIdx.x;
    const int tx  = tid & 15;
    const int ty  = tid >> 4;
    const int m0  = blockIdx.x * QKV_TM;

    unsigned long long accp[8][6];
    #pragma unroll
    for (int i = 0; i < 8; ++i)
        #pragma unroll
        for (int j = 0; j < 6; ++j) accp[i][j] = 0ull;

    for (int kc = 0; kc < 256; kc += 32) {
        #pragma unroll
        for (int it = 0; it < 8; ++it) {
            int idx = it * 128 + tid;
            int row = idx >> 3;
            int kq  = idx & 7;
            int gm  = m0 + row;
            float4 v = make_float4(0.f, 0.f, 0.f, 0.f);
            if (gm < nNodes)
                v = *reinterpret_cast<const float4*>(&X[gm * 256 + kc + kq * 4]);
            int kk = kq * 4;
            Xs[kk + 0][row] = v.x;
            Xs[kk + 1][row] = v.y;
            Xs[kk + 2][row] = v.z;
            Xs[kk + 3][row] = v.w;
        }
        #pragma unroll
        for (int idx = tid; idx < 32 * 96; idx += 128) {
            int k = idx / 96, j = idx - k * 96;
            const float* Wp = (j < 32) ? Wq : ((j < 64) ? Wk : Wv);
            Ws[k][j] = Wp[(kc + k) * 32 + (j & 31)];
        }
        __syncthreads();

        #pragma unroll
        for (int k = 0; k < 32; ++k) {
            float4 a0 = *reinterpret_cast<const float4*>(&Xs[k][tx * 4]);
            float4 a1 = *reinterpret_cast<const float4*>(&Xs[k][64 + tx * 4]);
            ulonglong2 b01 = *reinterpret_cast<const ulonglong2*>(&Ws[k][ty * 12]);
            ulonglong2 b23 = *reinterpret_cast<const ulonglong2*>(&Ws[k][ty * 12 + 4]);
            ulonglong2 b45 = *reinterpret_cast<const ulonglong2*>(&Ws[k][ty * 12 + 8]);
            unsigned long long bb[6] = {b01.x, b01.y, b23.x, b23.y, b45.x, b45.y};
            float av[8] = {a0.x, a0.y, a0.z, a0.w, a1.x, a1.y, a1.z, a1.w};
            #pragma unroll
            for (int i = 0; i < 8; ++i) {
                unsigned long long ad;
                asm("mov.b64 %0, {%1, %1};" : "=l"(ad) : "f"(av[i]));
                #pragma unroll
                for (int j = 0; j < 6; ++j)
                    asm("fma.rn.f32x2 %0, %1, %2, %0;"
                        : "+l"(accp[i][j]) : "l"(ad), "l"(bb[j]));
            }
        }
        __syncthreads();
    }

    const float qscale = 0.17677669529663687f;
    #pragma unroll
    for (int i = 0; i < 8; ++i) {
        int node = m0 + ((i < 4) ? (tx * 4 + i) : (64 + tx * 4 + i - 4));
        if (node >= nNodes) continue;
        #pragma unroll
        for (int j2 = 0; j2 < 6; ++j2) {
            float2 p = *reinterpret_cast<float2*>(&accp[i][j2]);
            int jj = ty * 12 + j2 * 2;
            float* dst = (jj < 32) ? g_Q : ((jj < 64) ? g_K : g_V);
            if (jj < 32) { p.x *= qscale; p.y *= qscale; }
            dst[node * 32 + (jj & 31)]     = p.x;
            dst[node * 32 + (jj & 31) + 1] = p.y;
        }
    }
}

// ---------------------------------------------------------------------------
__global__ void hist_kernel(const int* __restrict__ ei, int nEdges) {
    int i = blockIdx.x * blockDim.x + threadIdx.x;
    int e4 = i * 4;
    if (e4 + 3 < nEdges) {
        int4 r = *reinterpret_cast<const int4*>(&ei[e4]);
        atomicAdd(&g_cnt[r.x], 1);
        atomicAdd(&g_cnt[r.y], 1);
        atomicAdd(&g_cnt[r.z], 1);
        atomicAdd(&g_cnt[r.w], 1);
    } else {
        for (int e = e4; e < nEdges; ++e) atomicAdd(&g_cnt[ei[e]], 1);
    }
}

__global__ __launch_bounds__(1024) void scan_sum_kernel(int n) {
    int i = blockIdx.x * 1024 + threadIdx.x;
    int v = (i < n) ? g_cnt[i] : 0;
    #pragma unroll
    for (int o = 16; o; o >>= 1) v += __shfl_xor_sync(~0u, v, o);
    __shared__ int ws[32];
    if ((threadIdx.x & 31) == 0) ws[threadIdx.x >> 5] = v;
    __syncthreads();
    if (threadIdx.x < 32) {
        int s = ws[threadIdx.x];
        #pragma unroll
        for (int o = 16; o; o >>= 1) s += __shfl_xor_sync(~0u, s, o);
        if (threadIdx.x == 0) g_bsum[blockIdx.x] = s;
    }
}

__global__ void scan_base_kernel(int nb, int n) {
    __shared__ int sh[64];
    int t = threadIdx.x;
    int v = (t < nb) ? g_bsum[t] : 0;
    sh[t] = v;
    __syncthreads();
    #pragma unroll
    for (int o = 1; o < 64; o <<= 1) {
        int x = (t >= o) ? sh[t - o] : 0;
        __syncthreads();
        sh[t] += x;
        __syncthreads();
    }
    if (t < nb) g_bbase[t] = sh[t] - v;
    if (t == 63) g_off[n] = sh[63];
}

__global__ __launch_bounds__(1024) void scan_write_kernel(int n) {
    int i = blockIdx.x * 1024 + threadIdx.x;
    int lane = threadIdx.x & 31, w = threadIdx.x >> 5;
    int v = (i < n) ? g_cnt[i] : 0;
    int x = v;
    #pragma unroll
    for (int o = 1; o < 32; o <<= 1) {
        int y = __shfl_up_sync(~0u, x, o);
        if (lane >= o) x += y;
    }
    __shared__ int ws[32];
    if (lane == 31) ws[w] = x;
    __syncthreads();
    if (w == 0) {
        int s = ws[lane];
        #pragma unroll
        for (int o = 1; o < 32; o <<= 1) {
            int y = __shfl_up_sync(~0u, s, o);
            if (lane >= o) s += y;
        }
        ws[lane] = s;
    }
    __syncthreads();
    int base = g_bbase[blockIdx.x] + (w ? ws[w - 1] : 0);
    if (i < n) {
        int excl = base + x - v;
        g_off[i] = excl;
        g_cur[i] = excl;
    }
}

__global__ void scatter_kernel(const int* __restrict__ ei, int nEdges) {
    int i = blockIdx.x * blockDim.x + threadIdx.x;
    int e4 = i * 4;
    if (e4 + 3 < nEdges) {
        int4 r = *reinterpret_cast<const int4*>(&ei[e4]);
        int4 c = *reinterpret_cast<const int4*>(&ei[nEdges + e4]);
        g_sorted[atomicAdd(&g_cur[r.x], 1)] = c.x;
        g_sorted[atomicAdd(&g_cur[r.y], 1)] = c.y;
        g_sorted[atomicAdd(&g_cur[r.z], 1)] = c.z;
        g_sorted[atomicAdd(&g_cur[r.w], 1)] = c.w;
    } else {
        for (int e = e4; e < nEdges; ++e)
            g_sorted[atomicAdd(&g_cur[ei[e]], 1)] = ei[nEdges + e];
    }
}

// ---------------------------------------------------------------------------
// Attention, register-space. One warp per node.
// Lane layout: g = lane>>3 (row subgroup), c4 = lane&7 (4-col group).
// Tile of 32 edges: rows it*4+g, each lane loads K/V[row][c4*4..+3] (float4).
// Scores: dot4 + 3-level butterfly over c4; ex redistributed via 32-float smem.
// V: packed f32x2 accumulation; cross-lane column reduce ONCE at node end.
// ---------------------------------------------------------------------------
__global__ __launch_bounds__(256) void attn_kernel(float* __restrict__ out, int nNodes) {
    __shared__ float ssh[8][32];
    __shared__ float osh[8][32];

    const int wIn  = threadIdx.x >> 5;
    const int lane = threadIdx.x & 31;
    const int node = blockIdx.x * 8 + wIn;
    if (node >= nNodes) return;

    const int s = g_off[node];
    const int e = g_off[node + 1];

    const int c4 = lane & 7;
    const int g  = lane >> 3;

    float q = g_Q[node * 32 + lane];  // pre-scaled by 1/sqrt(32)
    // this lane's 4 q components (cols c4*4..c4*4+3)
    float qc0 = __shfl_sync(~0u, q, c4 * 4 + 0);
    float qc1 = __shfl_sync(~0u, q, c4 * 4 + 1);
    float qc2 = __shfl_sync(~0u, q, c4 * 4 + 2);
    float qc3 = __shfl_sync(~0u, q, c4 * 4 + 3);

    float denom = 0.f;
    unsigned long long accp0 = 0ull, accp1 = 0ull;  // cols c4*4..+3 partials

    for (int base = s; base < e; base += 32) {
        const int n = min(32, e - base);
        int cb = (base + lane < e) ? g_sorted[base + lane] : 0;

        // gather K and V fragments: 16 independent LDG.128
        float4 kr[8], vr[8];
        #pragma unroll
        for (int it = 0; it < 8; ++it) {
            int row = it * 4 + g;
            int c = __shfl_sync(~0u, cb, row);
            kr[it] = *reinterpret_cast<const float4*>(&g_K[c * 32 + c4 * 4]);
            vr[it] = *reinterpret_cast<const float4*>(&g_V[c * 32 + c4 * 4]);
        }

        // scores: per it, dot4 then butterfly over c4 (8 lanes per row)
        #pragma unroll
        for (int it = 0; it < 8; ++it) {
            float p = qc0 * kr[it].x;
            p = fmaf(qc1, kr[it].y, p);
            p = fmaf(qc2, kr[it].z, p);
            p = fmaf(qc3, kr[it].w, p);
            p += __shfl_xor_sync(~0u, p, 1);
            p += __shfl_xor_sync(~0u, p, 2);
            p += __shfl_xor_sync(~0u, p, 4);
            if (c4 == 0) ssh[wIn][it * 4 + g] = p;
        }
        __syncwarp();

        float ex = (lane < n) ? __expf(ssh[wIn][lane]) : 0.f;
        float t = ex;
        t += __shfl_xor_sync(~0u, t, 16);
        t += __shfl_xor_sync(~0u, t, 8);
        t += __shfl_xor_sync(~0u, t, 4);
        t += __shfl_xor_sync(~0u, t, 2);
        t += __shfl_xor_sync(~0u, t, 1);
        denom += t;

        // V accumulate: w = ex of this lane's row, packed f32x2 FMAs
        #pragma unroll
        for (int it = 0; it < 8; ++it) {
            float w = __shfl_sync(~0u, ex, it * 4 + g);
            unsigned long long wd;
            asm("mov.b64 %0, {%1, %1};" : "=l"(wd) : "f"(w));
            unsigned long long v01 = *reinterpret_cast<unsigned long long*>(&vr[it].x);
            unsigned long long v23 = *reinterpret_cast<unsigned long long*>(&vr[it].z);
            asm("fma.rn.f32x2 %0, %1, %2, %0;" : "+l"(accp0) : "l"(wd), "l"(v01));
            asm("fma.rn.f32x2 %0, %1, %2, %0;" : "+l"(accp1) : "l"(wd), "l"(v23));
        }
        __syncwarp();
    }

    // cross-lane reduce over g (bits 3,4) — once per node
    float a0 = reinterpret_cast<float2*>(&accp0)->x;
    float a1 = reinterpret_cast<float2*>(&accp0)->y;
    float a2 = reinterpret_cast<float2*>(&accp1)->x;
    float a3 = reinterpret_cast<float2*>(&accp1)->y;
    #pragma unroll
    for (int m = 8; m <= 16; m <<= 1) {
        a0 += __shfl_xor_sync(~0u, a0, m);
        a1 += __shfl_xor_sync(~0u, a1, m);
        a2 += __shfl_xor_sync(~0u, a2, m);
        a3 += __shfl_xor_sync(~0u, a3, m);
    }
    // all lanes in a c4-class now hold identical sums; benign same-value races
    osh[wIn][c4 * 4 + 0] = a0;
    osh[wIn][c4 * 4 + 1] = a1;
    osh[wIn][c4 * 4 + 2] = a2;
    osh[wIn][c4 * 4 + 3] = a3;
    __syncwarp();

    out[node * 32 + lane] = (e > s) ? (osh[wIn][lane] / denom) : 0.f;
}

// ---------------------------------------------------------------------------
// Launch: fork qkv onto a side stream so it overlaps the edge pipeline.
// ---------------------------------------------------------------------------
extern "C" void kernel_launch(void* const* d_in, const int* in_sizes, int n_in,
                              void* d_out, int out_size)
{
    const float* X  = (const float*)d_in[0];
    const float* Wq = (const float*)d_in[1];
    const float* Wk = (const float*)d_in[2];
    const float* Wv = (const float*)d_in[3];
    const int*   ei = (const int*)d_in[4];
    float* out = (float*)d_out;

    const int N = in_sizes[0] / 256;   // 50000
    const int E = in_sizes[4] / 2;     // 1600000
    const int NB = (N + 1023) / 1024;
    const int E4 = (E + 3) / 4;

    static cudaStream_t s2 = nullptr;
    static cudaEvent_t evFork = nullptr, evQkv = nullptr;
    if (!s2) {
        cudaStreamCreateWithFlags(&s2, cudaStreamNonBlocking);
        cudaEventCreateWithFlags(&evFork, cudaEventDisableTiming);
        cudaEventCreateWithFlags(&evQkv, cudaEventDisableTiming);
    }

    // fork: qkv on s2, edge pipeline on the main stream
    cudaEventRecord(evFork, 0);
    cudaStreamWaitEvent(s2, evFork, 0);
    qkv_kernel<<<(N + QKV_TM - 1) / QKV_TM, 128, 0, s2>>>(X, Wq, Wk, Wv, N);
    cudaEventRecord(evQkv, s2);

    zero_cnt_kernel<<<(N + 255) / 256, 256>>>(N);
    hist_kernel<<<(E4 + 255) / 256, 256>>>(ei, E);
    scan_sum_kernel<<<NB, 1024>>>(N);
    scan_base_kernel<<<1, 64>>>(NB, N);
    scan_write_kernel<<<NB, 1024>>>(N);
    scatter_kernel<<<(E4 + 255) / 256, 256>>>(ei, E);

    // join: attn needs both QKV and the sorted edge list
    cudaStreamWaitEvent(0, evQkv, 0);
    attn_kernel<<<(N + 7) / 8, 256>>>(out, N);
}